// round 14
// baseline (speedup 1.0000x reference)
#include <cuda_runtime.h>
#include <cuda_bf16.h>
#include <cuda_fp16.h>

// Problem sizes (fixed by the reference: B=4, L=512, D=256)
#define B 4
#define L 512
#define D 256
#define R_SIZE (B*L*D)        // 524288 floats (r)
#define A_SIZE (B*L*L)        // 1048576 floats (alpha)

#define TILE 64               // i/j tile for scores kernel
#define NT   (L/TILE)         // 8 tiles per dim
#define NPAIR (NT*(NT+1)/2)   // 36 upper-tri tile pairs per batch

#define CH   4                // d-chunks per batch (pipeline granularity)
#define DC   (D/CH)           // 64 dims per chunk
#define DC2  (DC/2)           // 32 half2 per chunk
#define SHC  34               // half2 row stride (34%32==2, conflict-free like 130)

// Partial scores, one buffer per d-chunk (summed by softmax): 16 MB
__device__ float g_part[CH][B*L*L];

__device__ __forceinline__ __half2 tanh2_approx(__half2 x) {
    unsigned xin = *reinterpret_cast<unsigned*>(&x);
    unsigned yout;
    asm("tanh.approx.f16x2 %0, %1;" : "=r"(yout) : "r"(xin));
    return *reinterpret_cast<__half2*>(&yout);
}

// ---------------------------------------------------------------------------
// Kernel 1 (per batch, per d-chunk): partial[b,i,j] = sum_{d in chunk}
// tanh(H[b,i,d]+H[b,j,d])*w[d].  (bias dropped: softmax shift-invariant)
// Round-6 proven inner loop (MUFU wall), restricted to a 64-dim chunk.
// Grid: 144 CTAs (36 upper-tri pairs x 4 chunks) x 512 thr -> full chip for
// one batch, ~1/4 of the MUFU wall per launch.
// ---------------------------------------------------------------------------
__global__ void __launch_bounds__(512)
scores_kernel(const float* __restrict__ H,
              const float* __restrict__ w,
              int b) {
    extern __shared__ __align__(16) unsigned smraw[];
    __half2* sHi = reinterpret_cast<__half2*>(smraw);   // 64 * SHC
    __half2* sHj = sHi + 64 * SHC;                      // 64 * SHC
    __half2* sWh = sHj + 64 * SHC;                      // DC2

    const int blk   = blockIdx.x;
    const int chunk = blk / NPAIR;       // 0..3
    int p = blk % NPAIR;
    int ti = 0, rowlen = NT;
    while (p >= rowlen) { p -= rowlen; ++ti; --rowlen; }
    const int tj = ti + p;
    const int i0 = ti * TILE;
    const int j0 = tj * TILE;
    const int dbase = chunk * DC;

    const int tid = threadIdx.x;
    const float* Hb = H + (size_t)b * L * D + dbase;

    if (tid < DC2) {
        float2 wv = reinterpret_cast<const float2*>(w + dbase)[tid];
        sWh[tid] = __float22half2_rn(wv);
    }

    // Load 64-row x 64-dim chunk tiles (16 float4 per row, 1024 f4 per tile)
    #pragma unroll
    for (int it = 0; it < 2; ++it) {
        int e = tid + 512 * it;
        int row = e >> 4;
        int c4  = e & 15;
        float4 v = *reinterpret_cast<const float4*>(Hb + (size_t)(i0 + row) * D + 4 * c4);
        sHi[row * SHC + 2 * c4]     = __floats2half2_rn(v.x, v.y);
        sHi[row * SHC + 2 * c4 + 1] = __floats2half2_rn(v.z, v.w);
    }
    #pragma unroll
    for (int it = 0; it < 2; ++it) {
        int e = tid + 512 * it;
        int row = e >> 4;
        int c4  = e & 15;
        float4 v = *reinterpret_cast<const float4*>(Hb + (size_t)(j0 + row) * D + 4 * c4);
        sHj[row * SHC + 2 * c4]     = __floats2half2_rn(v.x, v.y);
        sHj[row * SHC + 2 * c4 + 1] = __floats2half2_rn(v.z, v.w);
    }
    __syncthreads();

    const int tx = tid & 15;
    const int ty = tid >> 4;

    float accf[2][4];
    #pragma unroll
    for (int m = 0; m < 2; ++m)
        #pragma unroll
        for (int n = 0; n < 4; ++n) accf[m][n] = 0.0f;

    #pragma unroll 2
    for (int c = 0; c < DC2 / 4; ++c) {       // 8 chunks of 4 d-pairs
        __half2 acc2[2][4];
        #pragma unroll
        for (int m = 0; m < 2; ++m)
            #pragma unroll
            for (int n = 0; n < 4; ++n)
                acc2[m][n] = __halves2half2(__ushort_as_half(0), __ushort_as_half(0));

        #pragma unroll
        for (int u = 0; u < 4; ++u) {
            const int dp = 4 * c + u;
            const __half2 w2 = sWh[dp];
            __half2 hi[2], hj[4];
            #pragma unroll
            for (int m = 0; m < 2; ++m) hi[m] = sHi[(ty + 32 * m) * SHC + dp];
            #pragma unroll
            for (int n = 0; n < 4; ++n) hj[n] = sHj[(tx + 16 * n) * SHC + dp];
            #pragma unroll
            for (int m = 0; m < 2; ++m)
                #pragma unroll
                for (int n = 0; n < 4; ++n) {
                    __half2 t = tanh2_approx(__hadd2(hi[m], hj[n]));
                    acc2[m][n] = __hfma2(t, w2, acc2[m][n]);
                }
        }

        #pragma unroll
        for (int m = 0; m < 2; ++m)
            #pragma unroll
            for (int n = 0; n < 4; ++n) {
                float2 f = __half22float2(acc2[m][n]);
                accf[m][n] += f.x + f.y;
            }
    }

    float* Pg = g_part[chunk] + (size_t)b * L * L;
    const int mirror = (ti != tj);
    #pragma unroll
    for (int m = 0; m < 2; ++m) {
        int gi = i0 + ty + 32 * m;
        #pragma unroll
        for (int n = 0; n < 4; ++n) {
            int gj = j0 + tx + 16 * n;
            float v = accf[m][n];
            Pg[(size_t)gi * L + gj] = v;
            if (mirror)
                Pg[(size_t)gj * L + gi] = v;
        }
    }
}

// ---------------------------------------------------------------------------
// Kernel 2 (per batch): warp-per-row softmax over the SUM of the 4 partials.
// Grid: 64 CTAs x 256 thr = 512 warps = rows of one batch. 16 elems/lane.
// ---------------------------------------------------------------------------
__global__ void __launch_bounds__(256)
softmax_kernel(float* __restrict__ out_alpha, int b) {
    const int lane = threadIdx.x & 31;
    const int row  = blockIdx.x * 8 + (threadIdx.x >> 5);   // 0..511
    const size_t base = ((size_t)b * L + row) * L;

    const float4* P0 = reinterpret_cast<const float4*>(g_part[0] + base);
    const float4* P1 = reinterpret_cast<const float4*>(g_part[1] + base);
    const float4* P2 = reinterpret_cast<const float4*>(g_part[2] + base);
    const float4* P3 = reinterpret_cast<const float4*>(g_part[3] + base);

    float4 v[4];
    #pragma unroll
    for (int k = 0; k < 4; ++k) {
        int idx = lane + 32 * k;
        float4 a = P0[idx], c = P1[idx], d = P2[idx], e = P3[idx];
        v[k] = make_float4((a.x + c.x) + (d.x + e.x),
                           (a.y + c.y) + (d.y + e.y),
                           (a.z + c.z) + (d.z + e.z),
                           (a.w + c.w) + (d.w + e.w));
    }

    float mx = -1e30f;
    #pragma unroll
    for (int k = 0; k < 4; ++k)
        mx = fmaxf(mx, fmaxf(fmaxf(v[k].x, v[k].y), fmaxf(v[k].z, v[k].w)));
    #pragma unroll
    for (int o = 16; o; o >>= 1) mx = fmaxf(mx, __shfl_xor_sync(0xffffffffu, mx, o));

    float s = 0.0f;
    #pragma unroll
    for (int k = 0; k < 4; ++k) {
        v[k].x = __expf(v[k].x - mx); v[k].y = __expf(v[k].y - mx);
        v[k].z = __expf(v[k].z - mx); v[k].w = __expf(v[k].w - mx);
        s += (v[k].x + v[k].y) + (v[k].z + v[k].w);
    }
    #pragma unroll
    for (int o = 16; o; o >>= 1) s += __shfl_xor_sync(0xffffffffu, s, o);
    const float inv = 1.0f / s;

    float4* A4 = reinterpret_cast<float4*>(out_alpha + base);
    #pragma unroll
    for (int k = 0; k < 4; ++k) {
        float4 o4 = make_float4(v[k].x * inv, v[k].y * inv, v[k].z * inv, v[k].w * inv);
        A4[lane + 32 * k] = o4;
    }
}

// ---------------------------------------------------------------------------
// Kernel 3 (per batch): r[b] = alpha[b] (LxL) @ H[b] (LxD). Round-6 proven
// structure. Grid: (D/64, L/32) = 64 CTAs, 128 thr, double-buffered smem.
// ---------------------------------------------------------------------------
__global__ void __launch_bounds__(128)
gemm_kernel(const float* __restrict__ alpha,
            const float* __restrict__ H,
            float* __restrict__ r,
            int b) {
    __shared__ float As[2][32][36];   // [buf][k][i]
    __shared__ float Bs[2][32][68];   // [buf][k][d]

    const int i0 = blockIdx.y * 32;
    const int d0 = blockIdx.x * 64;

    const float* A  = alpha + (size_t)b * L * L;
    const float* Bm = H     + (size_t)b * L * D;
    float*       C  = r     + (size_t)b * L * D;

    const int tid = threadIdx.x;
    const int tx = tid & 15;
    const int ty = tid >> 4;

    float acc[4][4];
    #pragma unroll
    for (int m = 0; m < 4; ++m)
        #pragma unroll
        for (int n = 0; n < 4; ++n) acc[m][n] = 0.0f;

    #pragma unroll
    for (int t = 0; t < 2; ++t) {
        int e = tid + 128 * t;
        int ai = e >> 3, ak4 = e & 7;
        float4 v = *reinterpret_cast<const float4*>(A + (size_t)(i0 + ai) * L + 4 * ak4);
        As[0][4 * ak4 + 0][ai] = v.x;
        As[0][4 * ak4 + 1][ai] = v.y;
        As[0][4 * ak4 + 2][ai] = v.z;
        As[0][4 * ak4 + 3][ai] = v.w;
    }
    #pragma unroll
    for (int t = 0; t < 4; ++t) {
        int e = tid + 128 * t;
        int bk = e >> 4, bd4 = e & 15;
        float4 v = *reinterpret_cast<const float4*>(Bm + (size_t)bk * D + d0 + 4 * bd4);
        *reinterpret_cast<float4*>(&Bs[0][bk][4 * bd4]) = v;
    }
    __syncthreads();

    #pragma unroll 1
    for (int kt = 0; kt < 16; ++kt) {
        const int cur = kt & 1, nxt = cur ^ 1;

        float4 pa[2], pb[4];
        if (kt < 15) {
            const int k0n = (kt + 1) * 32;
            #pragma unroll
            for (int t = 0; t < 2; ++t) {
                int e = tid + 128 * t;
                int ai = e >> 3, ak4 = e & 7;
                pa[t] = *reinterpret_cast<const float4*>(A + (size_t)(i0 + ai) * L + k0n + 4 * ak4);
            }
            #pragma unroll
            for (int t = 0; t < 4; ++t) {
                int e = tid + 128 * t;
                int bk = e >> 4, bd4 = e & 15;
                pb[t] = *reinterpret_cast<const float4*>(Bm + (size_t)(k0n + bk) * D + d0 + 4 * bd4);
            }
        }

        #pragma unroll
        for (int kk = 0; kk < 32; ++kk) {
            float4 a = *reinterpret_cast<const float4*>(&As[cur][kk][ty * 4]);
            float4 bv = *reinterpret_cast<const float4*>(&Bs[cur][kk][tx * 4]);
            acc[0][0] = fmaf(a.x, bv.x, acc[0][0]);
            acc[0][1] = fmaf(a.x, bv.y, acc[0][1]);
            acc[0][2] = fmaf(a.x, bv.z, acc[0][2]);
            acc[0][3] = fmaf(a.x, bv.w, acc[0][3]);
            acc[1][0] = fmaf(a.y, bv.x, acc[1][0]);
            acc[1][1] = fmaf(a.y, bv.y, acc[1][1]);
            acc[1][2] = fmaf(a.y, bv.z, acc[1][2]);
            acc[1][3] = fmaf(a.y, bv.w, acc[1][3]);
            acc[2][0] = fmaf(a.z, bv.x, acc[2][0]);
            acc[2][1] = fmaf(a.z, bv.y, acc[2][1]);
            acc[2][2] = fmaf(a.z, bv.z, acc[2][2]);
            acc[2][3] = fmaf(a.z, bv.w, acc[2][3]);
            acc[3][0] = fmaf(a.w, bv.x, acc[3][0]);
            acc[3][1] = fmaf(a.w, bv.y, acc[3][1]);
            acc[3][2] = fmaf(a.w, bv.z, acc[3][2]);
            acc[3][3] = fmaf(a.w, bv.w, acc[3][3]);
        }

        if (kt < 15) {
            #pragma unroll
            for (int t = 0; t < 2; ++t) {
                int e = tid + 128 * t;
                int ai = e >> 3, ak4 = e & 7;
                As[nxt][4 * ak4 + 0][ai] = pa[t].x;
                As[nxt][4 * ak4 + 1][ai] = pa[t].y;
                As[nxt][4 * ak4 + 2][ai] = pa[t].z;
                As[nxt][4 * ak4 + 3][ai] = pa[t].w;
            }
            #pragma unroll
            for (int t = 0; t < 4; ++t) {
                int e = tid + 128 * t;
                int bk = e >> 4, bd4 = e & 15;
                *reinterpret_cast<float4*>(&Bs[nxt][bk][4 * bd4]) = pb[t];
            }
        }
        __syncthreads();
    }

    #pragma unroll
    for (int m = 0; m < 4; ++m) {
        int gi = i0 + ty * 4 + m;
        float4 v = make_float4(acc[m][0], acc[m][1], acc[m][2], acc[m][3]);
        *reinterpret_cast<float4*>(C + (size_t)gi * D + d0 + 4 * tx) = v;
    }
}

// ---------------------------------------------------------------------------
// Pipelined launch: scores_b on the (captured) legacy stream; softmax_b+gemm_b
// on a second stream gated by an event after scores_b -> tails overlap with
// scores_{b+1} on idle fma/LSU pipes. Final event joins back to legacy.
// Streams/events are created fresh each call (deterministic; host-side only).
// ---------------------------------------------------------------------------
extern "C" void kernel_launch(void* const* d_in, const int* in_sizes, int n_in,
                              void* d_out, int out_size) {
    const float* H = (const float*)d_in[0];
    const float* w = (const float*)d_in[1];

    float* out   = (float*)d_out;
    float* r     = out;            // first R_SIZE floats
    float* alpha = out + R_SIZE;   // next A_SIZE floats

    const int smem1 = (2 * 64 * SHC + DC2) * (int)sizeof(__half2);

    cudaStream_t s1;
    cudaStreamCreateWithFlags(&s1, cudaStreamNonBlocking);
    cudaEvent_t ev[B], done;
    for (int b = 0; b < B; ++b)
        cudaEventCreateWithFlags(&ev[b], cudaEventDisableTiming);
    cudaEventCreateWithFlags(&done, cudaEventDisableTiming);

    for (int b = 0; b < B; ++b) {
        scores_kernel<<<CH * NPAIR, 512, smem1>>>(H, w, b);
        cudaEventRecord(ev[b], 0);
        cudaStreamWaitEvent(s1, ev[b], 0);
        softmax_kernel<<<L / 8, 256, 0, s1>>>(alpha, b);
        gemm_kernel<<<dim3(D / 64, L / 32), 128, 0, s1>>>(alpha, H, r, b);
    }
    cudaEventRecord(done, s1);
    cudaStreamWaitEvent(0, done, 0);
}

// round 15
// speedup vs baseline: 1.7661x; 1.7661x over previous
#include <cuda_runtime.h>
#include <cuda_bf16.h>
#include <cuda_fp16.h>
#include <mma.h>

using namespace nvcuda;

// Problem sizes (fixed by the reference: B=4, L=512, D=256)
#define B 4
#define L 512
#define D 256
#define D2 (D/2)              // 128 half2 pairs
#define R_SIZE (B*L*D)        // 524288 floats (r)
#define A_SIZE (B*L*L)        // 1048576 floats (alpha)

#define TILE 64               // i/j tile for scores kernel
#define NT   (L/TILE)         // 8 tiles per dim
#define NPAIR (NT*(NT+1)/2)   // 36 upper-tri tile pairs per batch
#define SH2  130              // half2 row stride (proven conflict-free layout)
#define SCORES_GRID (B*NPAIR) // 144

// Scratch: fp32 pre-softmax scores; fp16 alpha & H for the tensor-core GEMM
__device__ float  g_scores[B*L*L];
__device__ __half g_alpha_h[A_SIZE];
__device__ __half g_H_h[R_SIZE];

__device__ __forceinline__ __half2 tanh2_approx(__half2 x) {
    unsigned xin = *reinterpret_cast<unsigned*>(&x);
    unsigned yout;
    asm("tanh.approx.f16x2 %0, %1;" : "=r"(yout) : "r"(xin));
    return *reinterpret_cast<__half2*>(&yout);
}

// ---------------------------------------------------------------------------
// Kernel 1 (round-6 proven, 39us = MUFU wall): scores[b,i,j] =
// sum_d tanh(H[b,i,d]+H[b,j,d])*w[d]  (bias dropped: softmax shift-invariant)
// Upper-tri 64x64 tiles, mirrored. Plus free H->fp16 copy (round-12 proven).
// ---------------------------------------------------------------------------
__global__ void __launch_bounds__(512)
scores_kernel(const float* __restrict__ H,
              const float* __restrict__ w) {
    extern __shared__ __align__(16) unsigned smraw[];
    __half2* sHi = reinterpret_cast<__half2*>(smraw);           // 64 * SH2
    __half2* sHj = sHi + 64 * SH2;                              // 64 * SH2
    __half2* sWh = sHj + 64 * SH2;                              // D2

    const int blk = blockIdx.x;
    const int b   = blk / NPAIR;
    int p = blk % NPAIR;
    int ti = 0, rowlen = NT;
    while (p >= rowlen) { p -= rowlen; ++ti; --rowlen; }
    const int tj = ti + p;
    const int i0 = ti * TILE;
    const int j0 = tj * TILE;

    const int tid = threadIdx.x;
    const float* Hb = H + (size_t)b * L * D;

    if (tid < D2) {
        float2 wv = reinterpret_cast<const float2*>(w)[tid];
        sWh[tid] = __float22half2_rn(wv);
    }

    // H -> fp16 copy (grid-stride; ~2 float4 per thread, hidden under MUFU)
    for (int idx = blk * 512 + tid; idx < R_SIZE / 4; idx += SCORES_GRID * 512) {
        float4 v = *reinterpret_cast<const float4*>(H + 4 * idx);
        __half2* dst = reinterpret_cast<__half2*>(g_H_h + 4 * idx);
        dst[0] = __floats2half2_rn(v.x, v.y);
        dst[1] = __floats2half2_rn(v.z, v.w);
    }

    #pragma unroll
    for (int it = 0; it < 8; ++it) {
        int e = tid + 512 * it;
        int row = e >> 6;
        int c4  = e & 63;
        float4 v = *reinterpret_cast<const float4*>(Hb + (size_t)(i0 + row) * D + 4 * c4);
        sHi[row * SH2 + 2 * c4]     = __floats2half2_rn(v.x, v.y);
        sHi[row * SH2 + 2 * c4 + 1] = __floats2half2_rn(v.z, v.w);
    }
    #pragma unroll
    for (int it = 0; it < 8; ++it) {
        int e = tid + 512 * it;
        int row = e >> 6;
        int c4  = e & 63;
        float4 v = *reinterpret_cast<const float4*>(Hb + (size_t)(j0 + row) * D + 4 * c4);
        sHj[row * SH2 + 2 * c4]     = __floats2half2_rn(v.x, v.y);
        sHj[row * SH2 + 2 * c4 + 1] = __floats2half2_rn(v.z, v.w);
    }
    __syncthreads();

    const int tx = tid & 15;
    const int ty = tid >> 4;

    float accf[2][4];
    #pragma unroll
    for (int m = 0; m < 2; ++m)
        #pragma unroll
        for (int n = 0; n < 4; ++n) accf[m][n] = 0.0f;

    #pragma unroll 2
    for (int c = 0; c < D2 / 4; ++c) {
        __half2 acc2[2][4];
        #pragma unroll
        for (int m = 0; m < 2; ++m)
            #pragma unroll
            for (int n = 0; n < 4; ++n)
                acc2[m][n] = __halves2half2(__ushort_as_half(0), __ushort_as_half(0));

        #pragma unroll
        for (int u = 0; u < 4; ++u) {
            const int dp = 4 * c + u;
            const __half2 w2 = sWh[dp];
            __half2 hi[2], hj[4];
            #pragma unroll
            for (int m = 0; m < 2; ++m) hi[m] = sHi[(ty + 32 * m) * SH2 + dp];
            #pragma unroll
            for (int n = 0; n < 4; ++n) hj[n] = sHj[(tx + 16 * n) * SH2 + dp];
            #pragma unroll
            for (int m = 0; m < 2; ++m)
                #pragma unroll
                for (int n = 0; n < 4; ++n) {
                    __half2 t = tanh2_approx(__hadd2(hi[m], hj[n]));
                    acc2[m][n] = __hfma2(t, w2, acc2[m][n]);
                }
        }

        #pragma unroll
        for (int m = 0; m < 2; ++m)
            #pragma unroll
            for (int n = 0; n < 4; ++n) {
                float2 f = __half22float2(acc2[m][n]);
                accf[m][n] += f.x + f.y;
            }
    }

    const int mirror = (ti != tj);
    #pragma unroll
    for (int m = 0; m < 2; ++m) {
        int gi = i0 + ty + 32 * m;
        #pragma unroll
        for (int n = 0; n < 4; ++n) {
            int gj = j0 + tx + 16 * n;
            float v = accf[m][n];
            g_scores[((size_t)b * L + gi) * L + gj] = v;
            if (mirror)
                g_scores[((size_t)b * L + gj) * L + gi] = v;
        }
    }
}

// ---------------------------------------------------------------------------
// Kernel 2: warp-per-row softmax; writes fp32 alpha (d_out) + fp16 alpha.
// Grid: 256 CTAs x 256 thr = 2048 warps = B*L rows. 16 elems/lane.
// ---------------------------------------------------------------------------
__global__ void __launch_bounds__(256)
softmax_kernel(float* __restrict__ out_alpha) {
    const int lane = threadIdx.x & 31;
    const int row  = blockIdx.x * 8 + (threadIdx.x >> 5);   // 0..2047
    const float4* S4 = reinterpret_cast<const float4*>(g_scores + (size_t)row * L);

    float4 v[4];
    #pragma unroll
    for (int k = 0; k < 4; ++k) v[k] = S4[lane + 32 * k];

    float mx = -1e30f;
    #pragma unroll
    for (int k = 0; k < 4; ++k)
        mx = fmaxf(mx, fmaxf(fmaxf(v[k].x, v[k].y), fmaxf(v[k].z, v[k].w)));
    #pragma unroll
    for (int o = 16; o; o >>= 1) mx = fmaxf(mx, __shfl_xor_sync(0xffffffffu, mx, o));

    float s = 0.0f;
    #pragma unroll
    for (int k = 0; k < 4; ++k) {
        v[k].x = __expf(v[k].x - mx); v[k].y = __expf(v[k].y - mx);
        v[k].z = __expf(v[k].z - mx); v[k].w = __expf(v[k].w - mx);
        s += (v[k].x + v[k].y) + (v[k].z + v[k].w);
    }
    #pragma unroll
    for (int o = 16; o; o >>= 1) s += __shfl_xor_sync(0xffffffffu, s, o);
    const float inv = 1.0f / s;

    float4* A4 = reinterpret_cast<float4*>(out_alpha + (size_t)row * L);
    __half2* Ah2 = reinterpret_cast<__half2*>(g_alpha_h + (size_t)row * L);
    #pragma unroll
    for (int k = 0; k < 4; ++k) {
        float4 o4 = make_float4(v[k].x * inv, v[k].y * inv, v[k].z * inv, v[k].w * inv);
        A4[lane + 32 * k] = o4;
        Ah2[2 * (lane + 32 * k)]     = __floats2half2_rn(o4.x, o4.y);
        Ah2[2 * (lane + 32 * k) + 1] = __floats2half2_rn(o4.z, o4.w);
    }
}

// ---------------------------------------------------------------------------
// Kernel 3: r[b] = alpha[b] @ H[b] on the tensor pipe, smem-staged.
// CTA: 64 i-rows x 128 d-cols; grid (2, 8, 4) = 64 CTAs, 256 thr (8 warps).
// Warp (wy,wx): 16-row x 64-col slab -> 4 m16n16k16 fp32 accum fragments.
// k-loop: 8 iters of 64; alpha (64x64) + H (64x128) tiles double-buffered
// in smem with register prefetch.
// ---------------------------------------------------------------------------
#define ALD 72    // alpha smem row stride (halves)
#define HLD 136   // H smem row stride (halves)
#define ATILE (64 * ALD)
#define HTILE (64 * HLD)

__global__ void __launch_bounds__(256)
gemm_wmma(float* __restrict__ out_r) {
    extern __shared__ __align__(16) __half wsm[];
    __half* As = wsm;              // 2 * ATILE
    __half* Bs = wsm + 2 * ATILE;  // 2 * HTILE

    const int d0  = blockIdx.x * 128;
    const int it0 = blockIdx.y * 64;
    const int b   = blockIdx.z;

    const __half* A  = g_alpha_h + ((size_t)b * L + it0) * L;      // 64 x 512
    const __half* Hm = g_H_h     + (size_t)b * L * D + d0;         // 512 x 128
    float*        C  = out_r     + ((size_t)b * L + it0) * D + d0;

    const int tid  = threadIdx.x;
    const int warp = tid >> 5;
    const int wy   = warp >> 1;    // 0..3: i-subtile (16 rows)
    const int wx   = warp & 1;     // 0..1: d-subtile (64 cols)

    wmma::fragment<wmma::accumulator, 16, 16, 16, float> acc[4];
    #pragma unroll
    for (int n = 0; n < 4; ++n) wmma::fill_fragment(acc[n], 0.0f);

    // prologue: k-tile 0
    #pragma unroll
    for (int t = 0; t < 2; ++t) {                 // alpha: 512 float4
        int e = tid + 256 * t;
        int row = e >> 3, c4 = e & 7;
        float4 v = *reinterpret_cast<const float4*>(A + (size_t)row * L + 8 * c4);
        *reinterpret_cast<float4*>(As + row * ALD + 8 * c4) = v;
    }
    #pragma unroll
    for (int t = 0; t < 4; ++t) {                 // H: 1024 float4
        int e = tid + 256 * t;
        int row = e >> 4, c4 = e & 15;
        float4 v = *reinterpret_cast<const float4*>(Hm + (size_t)row * D + 8 * c4);
        *reinterpret_cast<float4*>(Bs + row * HLD + 8 * c4) = v;
    }
    __syncthreads();

    #pragma unroll 1
    for (int kt = 0; kt < 8; ++kt) {
        const int cur = kt & 1, nxt = cur ^ 1;

        float4 pa[2], pb[4];
        if (kt < 7) {
            const int k0n = (kt + 1) * 64;
            #pragma unroll
            for (int t = 0; t < 2; ++t) {
                int e = tid + 256 * t;
                int row = e >> 3, c4 = e & 7;
                pa[t] = *reinterpret_cast<const float4*>(A + (size_t)row * L + k0n + 8 * c4);
            }
            #pragma unroll
            for (int t = 0; t < 4; ++t) {
                int e = tid + 256 * t;
                int row = e >> 4, c4 = e & 15;
                pb[t] = *reinterpret_cast<const float4*>(Hm + (size_t)(k0n + row) * D + 8 * c4);
            }
        }

        const __half* Ac = As + cur * ATILE;
        const __half* Bc = Bs + cur * HTILE;
        #pragma unroll
        for (int ks = 0; ks < 4; ++ks) {
            wmma::fragment<wmma::matrix_a, 16, 16, 16, __half, wmma::row_major> af;
            wmma::load_matrix_sync(af, Ac + (wy * 16) * ALD + ks * 16, ALD);
            #pragma unroll
            for (int n = 0; n < 4; ++n) {
                wmma::fragment<wmma::matrix_b, 16, 16, 16, __half, wmma::row_major> bf;
                wmma::load_matrix_sync(bf, Bc + (ks * 16) * HLD + wx * 64 + n * 16, HLD);
                wmma::mma_sync(acc[n], af, bf, acc[n]);
            }
        }

        if (kt < 7) {
            __half* An = As + nxt * ATILE;
            __half* Bn = Bs + nxt * HTILE;
            #pragma unroll
            for (int t = 0; t < 2; ++t) {
                int e = tid + 256 * t;
                int row = e >> 3, c4 = e & 7;
                *reinterpret_cast<float4*>(An + row * ALD + 8 * c4) = pa[t];
            }
            #pragma unroll
            for (int t = 0; t < 4; ++t) {
                int e = tid + 256 * t;
                int row = e >> 4, c4 = e & 15;
                *reinterpret_cast<float4*>(Bn + row * HLD + 8 * c4) = pb[t];
            }
        }
        __syncthreads();
    }

    #pragma unroll
    for (int n = 0; n < 4; ++n)
        wmma::store_matrix_sync(C + (size_t)(wy * 16) * D + wx * 64 + n * 16,
                                acc[n], D, wmma::mem_row_major);
}

// ---------------------------------------------------------------------------
extern "C" void kernel_launch(void* const* d_in, const int* in_sizes, int n_in,
                              void* d_out, int out_size) {
    const float* H = (const float*)d_in[0];
    const float* w = (const float*)d_in[1];

    float* out   = (float*)d_out;
    float* r     = out;            // first R_SIZE floats
    float* alpha = out + R_SIZE;   // next A_SIZE floats

    const int smem1 = (2 * 64 * SH2 + D2) * (int)sizeof(__half2);
    cudaFuncSetAttribute(scores_kernel,
                         cudaFuncAttributeMaxDynamicSharedMemorySize, smem1);

    const int smem3 = (2 * ATILE + 2 * HTILE) * (int)sizeof(__half);
    cudaFuncSetAttribute(gemm_wmma,
                         cudaFuncAttributeMaxDynamicSharedMemorySize, smem3);

    scores_kernel<<<SCORES_GRID, 512, smem1>>>(H, w);
    softmax_kernel<<<256, 256>>>(alpha);
    gemm_wmma<<<dim3(2, 8, 4), 256, smem3>>>(r);
}